// round 9
// baseline (speedup 1.0000x reference)
#include <cuda_runtime.h>
#include <cuda_bf16.h>
#include <cstdint>

// ===========================================================================
// GRU cell via mma.sync (sm_103 non-'a' target: tcgen05 unavailable).
// 3-term bf16 split: C = Ah*Bh + Al*Bh + Ah*Bl  (~2^-17 effective precision).
// R9: warp tile m32 x n8 -> 32 accumulator regs/thread (was 64) to relieve
// the 128-reg wall (spill hypothesis for the 440us plateau).
//   CTA tile M=128 x N=32, 512 threads = 16 warps (4m x 4n).
//   2-stage cp.async pipeline, K=64 per stage -> 16 barriers total.
// ===========================================================================

#define NT_COUNT 16          // 512 / 32
#define MT_COUNT 128         // 16384 / 128

// packed A: [mt 128][chunk 32][plane 2][row 128][64B]  = 64 MB
// packed W: [nt 16][gate 3][chunk 32][plane 2][n 32][64B] = 6 MB
__device__ __align__(128) unsigned char g_Apack[128u * 32u * 2u * 128u * 64u];
__device__ __align__(128) unsigned char g_Wpack[16u * 3u * 32u * 2u * 32u * 64u];

// smem stage layout, 144B row stride (36 banks -> conflict-free ldmatrix):
//   A plane p:  p*18432 + r*144                  (128 rows, 128B data = k64)
//   B gate g plane p: 36864 + ((g*2+p)*32 + n)*144
#define ROWB 144
#define STAGE_BYTES 64512
#define SMEM_TOTAL (2 * STAGE_BYTES)   // 129024

__device__ __forceinline__ uint32_t smem_u32(const void* p) {
    uint32_t a;
    asm("{ .reg .u64 t; cvta.to.shared.u64 t, %1; cvt.u32.u64 %0, t; }"
        : "=r"(a) : "l"(p));
    return a;
}

__device__ __forceinline__ void cp16(uint32_t dst, const void* src) {
    asm volatile("cp.async.cg.shared.global [%0], [%1], 16;"
                 :: "r"(dst), "l"(src) : "memory");
}
__device__ __forceinline__ void cp_commit() {
    asm volatile("cp.async.commit_group;" ::: "memory");
}
template <int N> __device__ __forceinline__ void cp_wait() {
    asm volatile("cp.async.wait_group %0;" :: "n"(N) : "memory");
}

__device__ __forceinline__ void ldm4(uint32_t r[4], uint32_t addr) {
    asm volatile("ldmatrix.sync.aligned.m8n8.x4.shared.b16 {%0,%1,%2,%3}, [%4];"
                 : "=r"(r[0]), "=r"(r[1]), "=r"(r[2]), "=r"(r[3]) : "r"(addr));
}
__device__ __forceinline__ void ldm2(uint32_t r[2], uint32_t addr) {
    asm volatile("ldmatrix.sync.aligned.m8n8.x2.shared.b16 {%0,%1}, [%2];"
                 : "=r"(r[0]), "=r"(r[1]) : "r"(addr));
}

__device__ __forceinline__ void mma16(float c[4], const uint32_t a[4],
                                      uint32_t b0, uint32_t b1) {
    asm volatile(
        "mma.sync.aligned.m16n8k16.row.col.f32.bf16.bf16.f32 "
        "{%0,%1,%2,%3}, {%4,%5,%6,%7}, {%8,%9}, {%0,%1,%2,%3};\n"
        : "+f"(c[0]), "+f"(c[1]), "+f"(c[2]), "+f"(c[3])
        : "r"(a[0]), "r"(a[1]), "r"(a[2]), "r"(a[3]), "r"(b0), "r"(b1));
}

__device__ __forceinline__ uint32_t pack_hi(float a, float b, uint32_t& lo) {
    __nv_bfloat16 ha = __float2bfloat16(a);
    __nv_bfloat16 hb = __float2bfloat16(b);
    float ra = a - __bfloat162float(ha);
    float rb = b - __bfloat162float(hb);
    __nv_bfloat162 hw; hw.x = ha; hw.y = hb;
    __nv_bfloat162 lw = __floats2bfloat162_rn(ra, rb);
    lo = *reinterpret_cast<uint32_t*>(&lw);
    return *reinterpret_cast<uint32_t*>(&hw);
}

// ---------------------------------------------------------------------------
// Merged pack kernel. Blocks [0,4096): A part (c = bx&31, mt = bx>>5).
// Blocks [4096,5632): W part, N-tile 32: w = bx-4096, c = w&31, ntg = w>>5
// (48 = 16 nt x 3 g).
__global__ __launch_bounds__(256) void pack_all(
    const float* __restrict__ x, const float* __restrict__ hs,
    const float* __restrict__ Wir, const float* __restrict__ Whr,
    const float* __restrict__ Wiz, const float* __restrict__ Whz,
    const float* __restrict__ Win, const float* __restrict__ Whn) {
    __shared__ float stg[32][33];
    const int bx = blockIdx.x;
    if (bx < 4096) {
        const int c = bx & 31, mt = bx >> 5;
        const float* S = (c < 16) ? x : hs;
        const int k0 = (c & 15) * 32;
        const size_t mrow = (size_t)mt * 128;
        unsigned char* hiP = g_Apack + ((size_t)(mt * 32 + c) * 2) * 8192;
        unsigned char* loP = hiP + 8192;
        #pragma unroll
        for (int it = 0; it < 8; ++it) {
            int id = it * 256 + threadIdx.x;   // 2048 float2
            int r = id >> 4, w = id & 15;
            float2 v = *reinterpret_cast<const float2*>(
                S + (mrow + r) * 512 + k0 + 2 * w);
            uint32_t lo, hi = pack_hi(v.x, v.y, lo);
            *reinterpret_cast<uint32_t*>(hiP + r * 64 + w * 4) = hi;
            *reinterpret_cast<uint32_t*>(loP + r * 64 + w * 4) = lo;
        }
    } else {
        const int w = bx - 4096;
        const int c = w & 31;
        const int ntg = w >> 5;                // 0..47
        const int nt = ntg / 3, g = ntg % 3;
        const float* W = (c < 16)
            ? ((g == 0) ? Wir : (g == 1) ? Wiz : Win)
            : ((g == 0) ? Whr : (g == 1) ? Whz : Whn);
        const int k0 = (c & 15) * 32, n0 = nt * 32;
        #pragma unroll
        for (int it = 0; it < 4; ++it) {       // 1024 floats: 32k x 32n
            int id = it * 256 + threadIdx.x;
            int k = id >> 5, n = id & 31;
            stg[k][n] = W[(size_t)(k0 + k) * 512 + n0 + n];
        }
        __syncthreads();
        unsigned char* hiP = g_Wpack + ((size_t)((nt * 3 + g) * 32 + c) * 2) * 2048;
        unsigned char* loP = hiP + 2048;
        #pragma unroll
        for (int it = 0; it < 2; ++it) {       // 512 word-pairs
            int id = it * 256 + threadIdx.x;
            int n = id >> 4, q = id & 15;
            uint32_t lo, hi = pack_hi(stg[2 * q][n], stg[2 * q + 1][n], lo);
            *reinterpret_cast<uint32_t*>(hiP + n * 64 + q * 4) = hi;
            *reinterpret_cast<uint32_t*>(loP + n * 64 + q * 4) = lo;
        }
    }
}

// ---------------------------------------------------------------------------
// issue one stage (chunks 2s, 2s+1): 3584 cp16 ops, 512 threads -> 7 iters.
// SMEM row holds k64: bytes [0,64) from chunk 2s, [64,128) from chunk 2s+1.
__device__ __forceinline__ void issue_stage(uint32_t sbase, int nt, int mt, int s) {
    const int tid = threadIdx.x;
    const int c0 = 2 * s;
    const unsigned char* Ac = g_Apack + ((size_t)(mt * 32 + c0) * 2) * 8192;
    #pragma unroll
    for (int it = 0; it < 7; ++it) {
        int id = it * 512 + tid;
        if (id < 2048) {                       // A: plane(2) x row(128) x ch(8)
            int p = id >> 10, rem = id & 1023;
            int r = rem >> 3, ch = rem & 7;
            int half = ch >> 2, cho = ch & 3;
            cp16(sbase + p * 18432 + r * ROWB + ch * 16,
                 Ac + (half * 2 + p) * 8192 + r * 64 + cho * 16);
        } else {                               // B: gp(6) x n(32) x ch(8)
            int v = id - 2048;
            int gp = v >> 8, rem = v & 255;
            int n = rem >> 3, ch = rem & 7;
            int half = ch >> 2, cho = ch & 3;
            int g = gp >> 1, p = gp & 1;
            cp16(sbase + 36864 + (gp * 32 + n) * ROWB + ch * 16,
                 g_Wpack + (((size_t)((nt * 3 + g) * 32 + c0 + half)) * 2 + p) * 2048
                         + n * 64 + cho * 16);
        }
    }
}

// One k16 step: 4 ldm4 (A) + 6 ldm2 (B) + 18 mma.
// Term-major, gate-interleaved: same-accumulator reuse distance = 6 HMMA.
__device__ __forceinline__ void compute_ks(
    uint32_t aAddr, uint32_t bAddr,
    float accR[2][4], float accZ[2][4], float accN[2][4]) {
    uint32_t Ah0[4], Ah1[4], Al0[4], Al1[4];
    ldm4(Ah0, aAddr);
    ldm4(Ah1, aAddr + 16 * ROWB);               // +16 rows
    ldm4(Al0, aAddr + 18432);                   // lo plane
    ldm4(Al1, aAddr + 18432 + 16 * ROWB);

    uint32_t BhR[2], BhZ[2], BhN[2], BlR[2], BlZ[2], BlN[2];
    ldm2(BhR, bAddr);                           // g0 hi
    ldm2(BlR, bAddr + 4608);                    // g0 lo (+32 rows)
    ldm2(BhZ, bAddr + 9216);                    // g1 hi
    ldm2(BlZ, bAddr + 13824);                   // g1 lo
    ldm2(BhN, bAddr + 18432);                   // g2 hi
    ldm2(BlN, bAddr + 23040);                   // g2 lo

    // term 1: Ah x Bh
    mma16(accR[0], Ah0, BhR[0], BhR[1]);
    mma16(accR[1], Ah1, BhR[0], BhR[1]);
    mma16(accZ[0], Ah0, BhZ[0], BhZ[1]);
    mma16(accZ[1], Ah1, BhZ[0], BhZ[1]);
    mma16(accN[0], Ah0, BhN[0], BhN[1]);
    mma16(accN[1], Ah1, BhN[0], BhN[1]);
    // term 2: Al x Bh
    mma16(accR[0], Al0, BhR[0], BhR[1]);
    mma16(accR[1], Al1, BhR[0], BhR[1]);
    mma16(accZ[0], Al0, BhZ[0], BhZ[1]);
    mma16(accZ[1], Al1, BhZ[0], BhZ[1]);
    mma16(accN[0], Al0, BhN[0], BhN[1]);
    mma16(accN[1], Al1, BhN[0], BhN[1]);
    // term 3: Ah x Bl
    mma16(accR[0], Ah0, BlR[0], BlR[1]);
    mma16(accR[1], Ah1, BlR[0], BlR[1]);
    mma16(accZ[0], Ah0, BlZ[0], BlZ[1]);
    mma16(accZ[1], Ah1, BlZ[0], BlZ[1]);
    mma16(accN[0], Ah0, BlN[0], BlN[1]);
    mma16(accN[1], Ah1, BlN[0], BlN[1]);
}

__global__ void __launch_bounds__(512, 1) gru_main(
    const float* __restrict__ hs,
    const float* __restrict__ br, const float* __restrict__ bz,
    const float* __restrict__ bn, float* __restrict__ out) {
    extern __shared__ unsigned char smem_raw[];
    const uint32_t smem = smem_u32(smem_raw);

    const int tid = threadIdx.x;
    const int wid = tid >> 5, lane = tid & 31;
    const int wm = (wid & 3) * 32;        // 0,32,64,96
    const int wn = (wid >> 2) * 8;        // 0,8,16,24
    const int nt = blockIdx.x;            // 0..15
    const int mt = blockIdx.y;            // 0..127

    const int rowA = (lane & 7) + ((lane >> 3) & 1) * 8;
    const int kbA  = (lane >> 4) * 16;
    const int rowB = lane & 7;
    const int kbB  = ((lane >> 3) & 1) * 16;
    const uint32_t aOff = (uint32_t)(wm + rowA) * ROWB + kbA;
    const uint32_t bOff = 36864u + (uint32_t)(wn + rowB) * ROWB + kbB;

    float aR[2][4] = {}, aZ[2][4] = {}, aNi[2][4] = {}, aNh[2][4] = {};

    issue_stage(smem, nt, mt, 0);
    cp_commit();

    // 2-stage: wait(s) -> sync -> compute ks0 -> issue(s+1) -> compute ks1..3
    for (int s = 0; s < 16; ++s) {
        cp_wait<0>();
        __syncthreads();
        const uint32_t sbase = smem + (s & 1) * STAGE_BYTES;
        const uint32_t aA = sbase + aOff;
        const uint32_t bA = sbase + bOff;
        if (s < 8) compute_ks(aA, bA, aR, aZ, aNi);
        else       compute_ks(aA, bA, aR, aZ, aNh);
        if (s + 1 < 16) {
            issue_stage(smem + ((s + 1) & 1) * STAGE_BYTES, nt, mt, s + 1);
            cp_commit();
        }
        #pragma unroll
        for (int ks = 1; ks < 4; ++ks) {
            if (s < 8) compute_ks(aA + ks * 32, bA + ks * 32, aR, aZ, aNi);
            else       compute_ks(aA + ks * 32, bA + ks * 32, aR, aZ, aNh);
        }
    }

    // ---- epilogue ----
    #pragma unroll
    for (int mi = 0; mi < 2; ++mi)
    #pragma unroll
    for (int i = 0; i < 4; ++i) {
        int rr = mt * 128 + wm + mi * 16 + (lane >> 2) + ((i >> 1) << 3);
        int cc = nt * 32 + wn + 2 * (lane & 3) + (i & 1);
        float pr = aR[mi][i] + __ldg(br + cc);
        float pz = aZ[mi][i] + __ldg(bz + cc);
        float rg = 1.0f / (1.0f + __expf(-pr));
        float zg = 1.0f / (1.0f + __expf(-pz));
        float ng = tanhf(aNi[mi][i] + rg * aNh[mi][i] + __ldg(bn + cc));
        float hv = hs[(size_t)rr * 512 + cc];
        out[(size_t)rr * 512 + cc] = (1.0f - zg) * ng + zg * hv;
    }
}

// ---------------------------------------------------------------------------
extern "C" void kernel_launch(void* const* d_in, const int* in_sizes, int n_in,
                              void* d_out, int out_size) {
    (void)in_sizes; (void)n_in; (void)out_size;
    const float* x   = (const float*)d_in[0];
    const float* h   = (const float*)d_in[1];
    const float* Wir = (const float*)d_in[2];
    const float* Whr = (const float*)d_in[3];
    const float* br  = (const float*)d_in[4];
    const float* Wiz = (const float*)d_in[5];
    const float* Whz = (const float*)d_in[6];
    const float* bz  = (const float*)d_in[7];
    const float* Win = (const float*)d_in[8];
    const float* Whn = (const float*)d_in[9];
    const float* bn  = (const float*)d_in[10];

    static_assert(SMEM_TOTAL == 129024, "smem layout");
    cudaFuncSetAttribute(gru_main, cudaFuncAttributeMaxDynamicSharedMemorySize,
                         SMEM_TOTAL);
    cudaFuncSetAttribute(gru_main, cudaFuncAttributePreferredSharedMemoryCarveout,
                         cudaSharedmemCarveoutMaxShared);

    pack_all<<<5632, 256>>>(x, h, Wir, Whr, Wiz, Whz, Win, Whn);
    gru_main<<<dim3(NT_COUNT, MT_COUNT), 512, SMEM_TOTAL>>>(
        h, br, bz, bn, (float*)d_out);
}

// round 10
// speedup vs baseline: 1.1839x; 1.1839x over previous
#include <cuda_runtime.h>
#include <cuda_bf16.h>
#include <cstdint>

// ===========================================================================
// GRU cell via mma.sync (sm_103 non-'a' target: tcgen05 unavailable).
// 3-term bf16 split: C = Ah*Bh + Al*Bh + Ah*Bl  (~2^-17 effective precision).
// R10: B operands loaded DIRECTLY from L2 via LDG.64 (no smem staging, no
// ldmatrix) -> cp.async op count cut 61% (LSU accept-rate was the limiter).
//   CTA tile M=128 x N=64, 512 threads = 16 warps (2m x 8n), warp m64 x n8.
//   A via 2-stage cp.async (K=64/stage). B double-buffered in regs, 1 k16
//   step of prefetch distance (~470cyc > L2 latency).
// ===========================================================================

#define NT_COUNT 8           // 512 / 64
#define MT_COUNT 128         // 16384 / 128

// packed A: [mt 128][chunk 32][plane 2][row 128][64B]  = 64 MB
__device__ __align__(128) unsigned char g_Apack[128u * 32u * 2u * 128u * 64u];
// packed W: [nt 8][gate 3][chunk 32][plane 2][k16half 2][n 64][32B] = 6 MB
//   32B per (n, k16): pairs stored as (q, q+4) adjacent -> one LDG.64 = {b0,b1}
__device__ __align__(128) unsigned char g_Wpack[8u * 3u * 32u * 2u * 2u * 64u * 32u];

// smem: A only. 144B row stride (36 banks -> conflict-free ldmatrix):
//   plane p: p*18432 + r*144   (128 rows, 128B data = k64)
#define ROWB 144
#define PLSTR 18432
#define STAGE_BYTES 36864
#define SMEM_TOTAL (2 * STAGE_BYTES)   // 73728

__device__ __forceinline__ uint32_t smem_u32(const void* p) {
    uint32_t a;
    asm("{ .reg .u64 t; cvta.to.shared.u64 t, %1; cvt.u32.u64 %0, t; }"
        : "=r"(a) : "l"(p));
    return a;
}

__device__ __forceinline__ void cp16(uint32_t dst, const void* src) {
    asm volatile("cp.async.cg.shared.global [%0], [%1], 16;"
                 :: "r"(dst), "l"(src) : "memory");
}
__device__ __forceinline__ void cp_commit() {
    asm volatile("cp.async.commit_group;" ::: "memory");
}
template <int N> __device__ __forceinline__ void cp_wait() {
    asm volatile("cp.async.wait_group %0;" :: "n"(N) : "memory");
}

__device__ __forceinline__ void ldm4(uint32_t r[4], uint32_t addr) {
    asm volatile("ldmatrix.sync.aligned.m8n8.x4.shared.b16 {%0,%1,%2,%3}, [%4];"
                 : "=r"(r[0]), "=r"(r[1]), "=r"(r[2]), "=r"(r[3]) : "r"(addr));
}

__device__ __forceinline__ void mma16(float c[4], const uint32_t a[4],
                                      uint32_t b0, uint32_t b1) {
    asm volatile(
        "mma.sync.aligned.m16n8k16.row.col.f32.bf16.bf16.f32 "
        "{%0,%1,%2,%3}, {%4,%5,%6,%7}, {%8,%9}, {%0,%1,%2,%3};\n"
        : "+f"(c[0]), "+f"(c[1]), "+f"(c[2]), "+f"(c[3])
        : "r"(a[0]), "r"(a[1]), "r"(a[2]), "r"(a[3]), "r"(b0), "r"(b1));
}

__device__ __forceinline__ uint32_t pack_hi(float a, float b, uint32_t& lo) {
    __nv_bfloat16 ha = __float2bfloat16(a);
    __nv_bfloat16 hb = __float2bfloat16(b);
    float ra = a - __bfloat162float(ha);
    float rb = b - __bfloat162float(hb);
    __nv_bfloat162 hw; hw.x = ha; hw.y = hb;
    __nv_bfloat162 lw = __floats2bfloat162_rn(ra, rb);
    lo = *reinterpret_cast<uint32_t*>(&lw);
    return *reinterpret_cast<uint32_t*>(&hw);
}

// ---------------------------------------------------------------------------
// Merged pack kernel. Blocks [0,4096): A (c = bx&31, mt = bx>>5).
// Blocks [4096,4864): W (w = bx-4096, c = w&31, ntg = w>>5; ntg = nt*3+g).
__global__ __launch_bounds__(256) void pack_all(
    const float* __restrict__ x, const float* __restrict__ hs,
    const float* __restrict__ Wir, const float* __restrict__ Whr,
    const float* __restrict__ Wiz, const float* __restrict__ Whz,
    const float* __restrict__ Win, const float* __restrict__ Whn) {
    __shared__ float stg[32][65];
    const int bx = blockIdx.x;
    if (bx < 4096) {
        const int c = bx & 31, mt = bx >> 5;
        const float* S = (c < 16) ? x : hs;
        const int k0 = (c & 15) * 32;
        const size_t mrow = (size_t)mt * 128;
        unsigned char* hiP = g_Apack + ((size_t)(mt * 32 + c) * 2) * 8192;
        unsigned char* loP = hiP + 8192;
        #pragma unroll
        for (int it = 0; it < 8; ++it) {
            int id = it * 256 + threadIdx.x;   // 2048 float2
            int r = id >> 4, w = id & 15;
            float2 v = *reinterpret_cast<const float2*>(
                S + (mrow + r) * 512 + k0 + 2 * w);
            uint32_t lo, hi = pack_hi(v.x, v.y, lo);
            *reinterpret_cast<uint32_t*>(hiP + r * 64 + w * 4) = hi;
            *reinterpret_cast<uint32_t*>(loP + r * 64 + w * 4) = lo;
        }
    } else {
        const int w = bx - 4096;
        const int c = w & 31;
        const int ntg = w >> 5;                // 0..23 = nt*3 + g
        const int nt = ntg / 3, g = ntg % 3;
        const float* W = (c < 16)
            ? ((g == 0) ? Wir : (g == 1) ? Wiz : Win)
            : ((g == 0) ? Whr : (g == 1) ? Whz : Whn);
        const int k0 = (c & 15) * 32, n0 = nt * 64;
        #pragma unroll
        for (int it = 0; it < 8; ++it) {       // 2048 floats: 32k x 64n
            int id = it * 256 + threadIdx.x;
            int k = id >> 6, n = id & 63;
            stg[k][n] = W[(size_t)(k0 + k) * 512 + n0 + n];
        }
        __syncthreads();
        // write: [plane 2][h 2][n 64][32B]; pair p at byte (p&3)*8 + (p>>2)*4
        unsigned char* base = g_Wpack + (size_t)(ntg * 32 + c) * 8192;
        #pragma unroll
        for (int it = 0; it < 4; ++it) {       // 1024 pairs: 64n x 16kp
            int id = it * 256 + threadIdx.x;
            int n = id >> 4, kp = id & 15;
            int h = kp >> 3, pl = kp & 7;
            int off = h * 2048 + n * 32 + (pl & 3) * 8 + (pl >> 2) * 4;
            uint32_t lo, hi = pack_hi(stg[2 * kp][n], stg[2 * kp + 1][n], lo);
            *reinterpret_cast<uint32_t*>(base + off) = hi;
            *reinterpret_cast<uint32_t*>(base + 4096 + off) = lo;
        }
    }
}

// ---------------------------------------------------------------------------
// issue one A stage (chunks 2s, 2s+1): 2048 cp16, 512 threads -> 4 iters.
__device__ __forceinline__ void issue_stage(uint32_t sbase, int mt, int s) {
    const int tid = threadIdx.x;
    const unsigned char* Ac = g_Apack + ((size_t)(mt * 32 + 2 * s) * 2) * 8192;
    #pragma unroll
    for (int it = 0; it < 4; ++it) {
        int id = it * 512 + tid;               // plane(2) x row(128) x ch(8)
        int p = id >> 10, rem = id & 1023;
        int r = rem >> 3, ch = rem & 7;
        int half = ch >> 2, cho = ch & 3;
        cp16(sbase + p * PLSTR + r * ROWB + ch * 16,
             Ac + (half * 2 + p) * 8192 + r * 64 + cho * 16);
    }
}

// Load 6 B fragments (3 gates x hi/lo) for global k16-step g (clamped).
// B[0]=g0 hi, B[1]=g0 lo, B[2]=g1 hi, B[3]=g1 lo, B[4]=g2 hi, B[5]=g2 lo.
__device__ __forceinline__ void ldB(uint2 B[6], const unsigned char* bp, int g) {
    int c = g >> 1; if (c > 31) c = 31;
    const unsigned char* p = bp + (size_t)c * 8192 + (size_t)(g & 1) * 2048;
    B[0] = __ldg(reinterpret_cast<const uint2*>(p));
    B[1] = __ldg(reinterpret_cast<const uint2*>(p + 4096));
    B[2] = __ldg(reinterpret_cast<const uint2*>(p + 262144));
    B[3] = __ldg(reinterpret_cast<const uint2*>(p + 262144 + 4096));
    B[4] = __ldg(reinterpret_cast<const uint2*>(p + 524288));
    B[5] = __ldg(reinterpret_cast<const uint2*>(p + 524288 + 4096));
}

// One m32-half: 4 ldm4 + 18 mma (gate-interleaved, acc reuse distance 6).
__device__ __forceinline__ void half_mma(
    uint32_t aA, const uint2 B[6],
    float aR0[4], float aR1[4], float aZ0[4], float aZ1[4],
    float aN0[4], float aN1[4]) {
    uint32_t Ah0[4], Ah1[4], Al0[4], Al1[4];
    ldm4(Ah0, aA);
    ldm4(Ah1, aA + 16 * ROWB);
    ldm4(Al0, aA + PLSTR);
    ldm4(Al1, aA + PLSTR + 16 * ROWB);
    // term 1: Ah x Bh
    mma16(aR0, Ah0, B[0].x, B[0].y);  mma16(aR1, Ah1, B[0].x, B[0].y);
    mma16(aZ0, Ah0, B[2].x, B[2].y);  mma16(aZ1, Ah1, B[2].x, B[2].y);
    mma16(aN0, Ah0, B[4].x, B[4].y);  mma16(aN1, Ah1, B[4].x, B[4].y);
    // term 2: Al x Bh
    mma16(aR0, Al0, B[0].x, B[0].y);  mma16(aR1, Al1, B[0].x, B[0].y);
    mma16(aZ0, Al0, B[2].x, B[2].y);  mma16(aZ1, Al1, B[2].x, B[2].y);
    mma16(aN0, Al0, B[4].x, B[4].y);  mma16(aN1, Al1, B[4].x, B[4].y);
    // term 3: Ah x Bl
    mma16(aR0, Ah0, B[1].x, B[1].y);  mma16(aR1, Ah1, B[1].x, B[1].y);
    mma16(aZ0, Ah0, B[3].x, B[3].y);  mma16(aZ1, Ah1, B[3].x, B[3].y);
    mma16(aN0, Ah0, B[5].x, B[5].y);  mma16(aN1, Ah1, B[5].x, B[5].y);
}

#define STEP(KS, CUR, NXT, AN)                                            \
    do {                                                                  \
        ldB(NXT, bp, 4 * s + (KS) + 1);                                   \
        half_mma(aA + (KS) * 32, CUR,                                     \
                 aR[0], aR[1], aZ[0], aZ[1], AN[0], AN[1]);               \
        half_mma(aA + (KS) * 32 + 32 * ROWB, CUR,                         \
                 aR[2], aR[3], aZ[2], aZ[3], AN[2], AN[3]);               \
    } while (0)

__global__ void __launch_bounds__(512, 1) gru_main(
    const float* __restrict__ hs,
    const float* __restrict__ br, const float* __restrict__ bz,
    const float* __restrict__ bn, float* __restrict__ out) {
    extern __shared__ unsigned char smem_raw[];
    const uint32_t smem = smem_u32(smem_raw);

    const int tid = threadIdx.x;
    const int wid = tid >> 5, lane = tid & 31;
    const int wm = (wid & 1) * 64;        // 0,64
    const int wn = (wid >> 1) * 8;        // 0..56
    const int nt = blockIdx.x;            // 0..7
    const int mt = blockIdx.y;            // 0..127

    const int rowA = (lane & 7) + ((lane >> 3) & 1) * 8;
    const int kbA  = (lane >> 4) * 16;
    const uint32_t aOff = (uint32_t)(wm + rowA) * ROWB + kbA;
    const unsigned char* bp = g_Wpack + (size_t)nt * 786432
        + (size_t)(wn + (lane >> 2)) * 32 + (size_t)(lane & 3) * 8;

    float aR[4][4] = {}, aZ[4][4] = {}, aNi[4][4] = {}, aNh[4][4] = {};
    uint2 B0[6], B1[6];

    issue_stage(smem, mt, 0);
    cp_commit();
    ldB(B0, bp, 0);

    for (int s = 0; s < 16; ++s) {
        cp_wait<0>();
        __syncthreads();
        const uint32_t aA = smem + (s & 1) * STAGE_BYTES + aOff;
        if (s < 8) STEP(0, B0, B1, aNi); else STEP(0, B0, B1, aNh);
        if (s + 1 < 16) {
            issue_stage(smem + ((s + 1) & 1) * STAGE_BYTES, mt, s + 1);
            cp_commit();
        }
        if (s < 8) { STEP(1, B1, B0, aNi); STEP(2, B0, B1, aNi); STEP(3, B1, B0, aNi); }
        else       { STEP(1, B1, B0, aNh); STEP(2, B0, B1, aNh); STEP(3, B1, B0, aNh); }
    }

    // ---- epilogue ----
    #pragma unroll
    for (int mtile = 0; mtile < 4; ++mtile)
    #pragma unroll
    for (int i = 0; i < 4; ++i) {
        int rr = mt * 128 + wm + mtile * 16 + (lane >> 2) + ((i >> 1) << 3);
        int cc = nt * 64 + wn + 2 * (lane & 3) + (i & 1);
        float pr = aR[mtile][i] + __ldg(br + cc);
        float pz = aZ[mtile][i] + __ldg(bz + cc);
        float rg = 1.0f / (1.0f + __expf(-pr));
        float zg = 1.0f / (1.0f + __expf(-pz));
        float ng = tanhf(aNi[mtile][i] + rg * aNh[mtile][i] + __ldg(bn + cc));
        float hv = hs[(size_t)rr * 512 + cc];
        out[(size_t)rr * 512 + cc] = (1.0f - zg) * ng + zg * hv;
    }
}

// ---------------------------------------------------------------------------
extern "C" void kernel_launch(void* const* d_in, const int* in_sizes, int n_in,
                              void* d_out, int out_size) {
    (void)in_sizes; (void)n_in; (void)out_size;
    const float* x   = (const float*)d_in[0];
    const float* h   = (const float*)d_in[1];
    const float* Wir = (const float*)d_in[2];
    const float* Whr = (const float*)d_in[3];
    const float* br  = (const float*)d_in[4];
    const float* Wiz = (const float*)d_in[5];
    const float* Whz = (const float*)d_in[6];
    const float* bz  = (const float*)d_in[7];
    const float* Win = (const float*)d_in[8];
    const float* Whn = (const float*)d_in[9];
    const float* bn  = (const float*)d_in[10];

    static_assert(SMEM_TOTAL == 73728, "smem layout");
    cudaFuncSetAttribute(gru_main, cudaFuncAttributeMaxDynamicSharedMemorySize,
                         SMEM_TOTAL);
    cudaFuncSetAttribute(gru_main, cudaFuncAttributePreferredSharedMemoryCarveout,
                         cudaSharedmemCarveoutMaxShared);

    pack_all<<<4864, 256>>>(x, h, Wir, Whr, Wiz, Whz, Win, Whn);
    gru_main<<<dim3(NT_COUNT, MT_COUNT), 512, SMEM_TOTAL>>>(
        h, br, bz, bn, (float*)d_out);
}